// round 1
// baseline (speedup 1.0000x reference)
#include <cuda_runtime.h>

#define NB 4
#define NXg 432
#define NYg 496
#define Hc 248
#define Wc 216
#define HW (Hc*Wc)
#define C1 8
#define C2 16
#define COUT 400
#define CSP 384
#define KS 15
#define RAD 7
#define NBN (NB*HW)

// scratch (device globals; no allocation allowed)
__device__ float g_hist[NB*NYg*NXg];
__device__ float g_tmp [NB*NYg*NXg];
__device__ float g_dm  [NB*HW];
__device__ float g_c1  [NB*C1*HW];
__device__ float g_c2  [NB*C2*HW];
__device__ float g_gauss[KS];
__device__ int   g_max[NB];              // float bits, values >= 0
__device__ float g_stats1[2*C1];         // sum, sumsq
__device__ float g_stats2[2*C2];
__device__ float g_bn1[2*C1];            // scale, shift
__device__ float g_bn2[2*C2];

__global__ void k_init() {
    int i = blockIdx.x*blockDim.x + threadIdx.x;
    if (i < NB*NYg*NXg) g_hist[i] = 0.f;
    if (i < KS) {
        const float sig = 6.25f;
        float s = 0.f;
        for (int k = 0; k < KS; k++) {
            float c = (float)(k - RAD);
            s += expf(-c*c/(2.f*sig*sig));
        }
        float c = (float)(i - RAD);
        g_gauss[i] = expf(-c*c/(2.f*sig*sig)) / s;
    }
    if (i < NB)   g_max[i] = 0;
    if (i < 2*C1) g_stats1[i] = 0.f;
    if (i < 2*C2) g_stats2[i] = 0.f;
}

__global__ void k_hist(const float* __restrict__ pts, int n) {
    int i = blockIdx.x*blockDim.x + threadIdx.x;
    if (i >= n) return;
    const float* p = pts + (size_t)i*5;
    int b = (int)p[0];
    int x = (int)__fdiv_rn(p[1] - 0.0f,  0.16f);
    int y = (int)__fdiv_rn(p[2] + 39.68f, 0.16f);
    x = min(max(x, 0), NXg-1);
    y = min(max(y, 0), NYg-1);
    atomicAdd(&g_hist[(b*NYg + y)*NXg + x], 1.0f);
}

__global__ void k_blur_x() {
    int i = blockIdx.x*blockDim.x + threadIdx.x;
    if (i >= NB*NYg*NXg) return;
    int x = i % NXg;
    int row = i / NXg;  // b*NYg + y
    float acc = 0.f;
    #pragma unroll
    for (int k = 0; k < KS; k++) {
        int xx = x + k - RAD;
        if (xx >= 0 && xx < NXg)
            acc += g_gauss[k] * g_hist[row*NXg + xx];
    }
    g_tmp[i] = acc;
}

__global__ void k_blur_y() {
    int i = blockIdx.x*blockDim.x + threadIdx.x;
    if (i >= NB*NYg*NXg) return;
    int x = i % NXg;
    int y = (i / NXg) % NYg;
    int b = i / (NXg*NYg);
    float acc = 0.f;
    #pragma unroll
    for (int k = 0; k < KS; k++) {
        int yy = y + k - RAD;
        if (yy >= 0 && yy < NYg)
            acc += g_gauss[k] * g_tmp[(b*NYg + yy)*NXg + x];
    }
    g_hist[i] = acc;   // blurred result back into g_hist
}

__global__ void k_max() {
    int b = blockIdx.y;
    float m = 0.f;
    for (int i = blockIdx.x*blockDim.x + threadIdx.x; i < NYg*NXg;
         i += gridDim.x*blockDim.x)
        m = fmaxf(m, g_hist[b*NYg*NXg + i]);
    __shared__ float sm[256];
    sm[threadIdx.x] = m; __syncthreads();
    for (int s = 128; s > 0; s >>= 1) {
        if (threadIdx.x < s) sm[threadIdx.x] = fmaxf(sm[threadIdx.x], sm[threadIdx.x+s]);
        __syncthreads();
    }
    if (threadIdx.x == 0) atomicMax(&g_max[b], __float_as_int(sm[0]));
}

// jax.image.resize 'linear' antialias=True, 2x downsample:
// taps at 2i-1..2i+2 with weights [1,3,3,1], edge-clipped + renormalized.
__device__ __forceinline__ void taps4(int i, int n, int* j, float* w) {
    const float base[4] = {1.f, 3.f, 3.f, 1.f};
    float s = 0.f;
    #pragma unroll
    for (int k = 0; k < 4; k++) {
        int jj = 2*i - 1 + k;
        j[k] = jj;
        if (jj >= 0 && jj < n) { w[k] = base[k]; s += base[k]; }
        else w[k] = 0.f;
    }
    #pragma unroll
    for (int k = 0; k < 4; k++) w[k] /= s;
}

__global__ void k_down() {
    int i = blockIdx.x*blockDim.x + threadIdx.x;
    if (i >= NB*HW) return;
    int x = i % Wc;
    int y = (i / Wc) % Hc;
    int b = i / HW;
    int jy[4], jx[4]; float wy[4], wx[4];
    taps4(y, NYg, jy, wy);
    taps4(x, NXg, jx, wx);
    float acc = 0.f;
    #pragma unroll
    for (int a = 0; a < 4; a++) {
        if (wy[a] == 0.f) continue;
        float r = 0.f;
        #pragma unroll
        for (int c = 0; c < 4; c++) {
            if (wx[c] == 0.f) continue;
            r += wx[c] * g_hist[(b*NYg + jy[a])*NXg + jx[c]];
        }
        acc += wy[a] * r;
    }
    float mx = __int_as_float(g_max[b]);
    g_dm[i] = (mx > 0.f) ? acc / mx : acc;
}

__global__ void k_conv1(const float* __restrict__ w1) {
    int bc = blockIdx.y;                 // b*C1 + c
    int b = bc / C1, c = bc % C1;
    int hw = blockIdx.x*blockDim.x + threadIdx.x;
    float v = 0.f;
    if (hw < HW) {
        int x = hw % Wc, y = hw / Wc;
        const float* wp = w1 + c*9;
        const float* in = g_dm + b*HW;
        #pragma unroll
        for (int dy = 0; dy < 3; dy++) {
            int yy = y + dy - 1;
            if (yy < 0 || yy >= Hc) continue;
            #pragma unroll
            for (int dx = 0; dx < 3; dx++) {
                int xx = x + dx - 1;
                if (xx < 0 || xx >= Wc) continue;
                v = fmaf(__ldg(&wp[dy*3+dx]), in[yy*Wc+xx], v);
            }
        }
        g_c1[bc*HW + hw] = v;
    }
    __shared__ float s1[256], s2[256];
    float vv = (hw < HW) ? v : 0.f;
    s1[threadIdx.x] = vv; s2[threadIdx.x] = vv*vv;
    __syncthreads();
    for (int s = 128; s > 0; s >>= 1) {
        if (threadIdx.x < s) { s1[threadIdx.x] += s1[threadIdx.x+s]; s2[threadIdx.x] += s2[threadIdx.x+s]; }
        __syncthreads();
    }
    if (threadIdx.x == 0) {
        atomicAdd(&g_stats1[c], s1[0]);
        atomicAdd(&g_stats1[C1 + c], s2[0]);
    }
}

__global__ void k_bnp1(const float* __restrict__ gamma, const float* __restrict__ beta) {
    int c = threadIdx.x;
    if (c >= C1) return;
    float mean = g_stats1[c] / (float)NBN;
    float var  = g_stats1[C1+c] / (float)NBN - mean*mean;
    float inv  = rsqrtf(var + 1e-3f);
    float sc   = gamma[c] * inv;
    g_bn1[c] = sc;
    g_bn1[C1+c] = beta[c] - mean*sc;
}

__global__ void k_relu1() {
    int i = blockIdx.x*blockDim.x + threadIdx.x;
    if (i >= NB*C1*HW) return;
    int c = (i / HW) % C1;
    g_c1[i] = fmaxf(fmaf(g_c1[i], g_bn1[c], g_bn1[C1+c]), 0.f);
}

__global__ void k_conv2(const float* __restrict__ w2) {
    int bc = blockIdx.y;                 // b*C2 + co
    int b = bc / C2, co = bc % C2;
    __shared__ float ws[C1*9];
    if (threadIdx.x < C1*9) ws[threadIdx.x] = w2[co*C1*9 + threadIdx.x];
    __syncthreads();
    int hw = blockIdx.x*blockDim.x + threadIdx.x;
    float v = 0.f;
    if (hw < HW) {
        int x = hw % Wc, y = hw / Wc;
        #pragma unroll
        for (int ci = 0; ci < C1; ci++) {
            const float* in = g_c1 + (b*C1 + ci)*HW;
            const float* wp = ws + ci*9;
            #pragma unroll
            for (int dy = 0; dy < 3; dy++) {
                int yy = y + dy - 1;
                if (yy < 0 || yy >= Hc) continue;
                #pragma unroll
                for (int dx = 0; dx < 3; dx++) {
                    int xx = x + dx - 1;
                    if (xx < 0 || xx >= Wc) continue;
                    v = fmaf(wp[dy*3+dx], in[yy*Wc+xx], v);
                }
            }
        }
        g_c2[bc*HW + hw] = v;
    }
    __shared__ float s1[256], s2[256];
    float vv = (hw < HW) ? v : 0.f;
    s1[threadIdx.x] = vv; s2[threadIdx.x] = vv*vv;
    __syncthreads();
    for (int s = 128; s > 0; s >>= 1) {
        if (threadIdx.x < s) { s1[threadIdx.x] += s1[threadIdx.x+s]; s2[threadIdx.x] += s2[threadIdx.x+s]; }
        __syncthreads();
    }
    if (threadIdx.x == 0) {
        atomicAdd(&g_stats2[co], s1[0]);
        atomicAdd(&g_stats2[C2 + co], s2[0]);
    }
}

__global__ void k_bnp2(const float* __restrict__ gamma, const float* __restrict__ beta) {
    int c = threadIdx.x;
    if (c >= C2) return;
    float mean = g_stats2[c] / (float)NBN;
    float var  = g_stats2[C2+c] / (float)NBN - mean*mean;
    float inv  = rsqrtf(var + 1e-3f);
    float sc   = gamma[c] * inv;
    g_bn2[c] = sc;
    g_bn2[C2+c] = beta[c] - mean*sc;
}

__global__ void k_out(float* __restrict__ out) {
    int i = blockIdx.x*blockDim.x + threadIdx.x;
    if (i >= NB*C2*HW) return;
    int hw = i % HW;
    int c  = (i / HW) % C2;
    int b  = i / (C2*HW);
    float v = fmaxf(fmaf(g_c2[i], g_bn2[c], g_bn2[C2+c]), 0.f);
    out[((size_t)b*COUT + CSP + c)*HW + hw] = v;
}

extern "C" void kernel_launch(void* const* d_in, const int* in_sizes, int n_in,
                              void* d_out, int out_size) {
    const float* spatial = (const float*)d_in[0];
    const float* points  = (const float*)d_in[1];
    const float* w1      = (const float*)d_in[2];
    const float* gamma1  = (const float*)d_in[3];
    const float* beta1   = (const float*)d_in[4];
    const float* w2      = (const float*)d_in[5];
    const float* gamma2  = (const float*)d_in[6];
    const float* beta2   = (const float*)d_in[7];
    float* out = (float*)d_out;
    int npts = in_sizes[1] / 5;

    // Concat: copy the 384 spatial channels per batch (contiguous slabs, peak-BW path)
    for (int b = 0; b < NB; b++)
        cudaMemcpyAsync(out + (size_t)b*COUT*HW,
                        spatial + (size_t)b*CSP*HW,
                        (size_t)CSP*HW*sizeof(float),
                        cudaMemcpyDeviceToDevice, 0);

    int total = NB*NYg*NXg;
    k_init  <<<(total + 255)/256, 256>>>();
    k_hist  <<<(npts + 255)/256, 256>>>(points, npts);
    k_blur_x<<<(total + 255)/256, 256>>>();
    k_blur_y<<<(total + 255)/256, 256>>>();
    { dim3 g(104, NB); k_max<<<g, 256>>>(); }
    k_down  <<<(NB*HW + 255)/256, 256>>>();
    { dim3 g((HW + 255)/256, NB*C1); k_conv1<<<g, 256>>>(w1); }
    k_bnp1  <<<1, 32>>>(gamma1, beta1);
    k_relu1 <<<(NB*C1*HW + 255)/256, 256>>>();
    { dim3 g((HW + 255)/256, NB*C2); k_conv2<<<g, 256>>>(w2); }
    k_bnp2  <<<1, 32>>>(gamma2, beta2);
    k_out   <<<(NB*C2*HW + 255)/256, 256>>>(out);
}

// round 2
// speedup vs baseline: 1.0561x; 1.0561x over previous
#include <cuda_runtime.h>

#define NB 4
#define NXg 432
#define NYg 496
#define Hc 248
#define Wc 216
#define HW (Hc*Wc)
#define C1 8
#define C2 16
#define COUT 400
#define CSP 384
#define KS 15
#define RAD 7
#define NBN (NB*HW)

// scratch (device globals; no allocation allowed)
__device__ float g_hist[NB*NYg*NXg];
__device__ float g_tmp [NB*NYg*NXg];
__device__ float g_dm  [NB*HW];
__device__ float g_c1  [NB*C1*HW];
__device__ float g_c2  [NB*C2*HW];
__device__ float g_gauss[KS];
__device__ int   g_max[NB];              // float bits, values >= 0
__device__ float g_stats1[2*C1];         // sum, sumsq
__device__ float g_stats2[2*C2];
__device__ float g_bn1[2*C1];            // scale, shift
__device__ float g_bn2[2*C2];

// ---------------- concat copy: 384 spatial channels, float4 streaming ----------------
__global__ void k_copy(const float4* __restrict__ src, float4* __restrict__ dst) {
    const int per   = CSP*HW/4;          // float4s per batch slab = 5142528
    const int stride = gridDim.x*blockDim.x;
    for (int b = 0; b < NB; b++) {
        const float4* s = src + (size_t)b*per;
        float4*       d = dst + (size_t)b*(COUT*HW/4);
        for (int i = blockIdx.x*blockDim.x + threadIdx.x; i < per; i += stride)
            d[i] = s[i];
    }
}

__global__ void k_init() {
    int i = blockIdx.x*blockDim.x + threadIdx.x;
    if (i < NB*NYg*NXg) g_hist[i] = 0.f;
    if (i < KS) {
        const float sig = 6.25f;
        float s = 0.f;
        for (int k = 0; k < KS; k++) {
            float c = (float)(k - RAD);
            s += expf(-c*c/(2.f*sig*sig));
        }
        float c = (float)(i - RAD);
        g_gauss[i] = expf(-c*c/(2.f*sig*sig)) / s;
    }
    if (i < NB)   g_max[i] = 0;
    if (i < 2*C1) g_stats1[i] = 0.f;
    if (i < 2*C2) g_stats2[i] = 0.f;
}

__global__ void k_hist(const float* __restrict__ pts, int n) {
    int i = blockIdx.x*blockDim.x + threadIdx.x;
    if (i >= n) return;
    const float* p = pts + (size_t)i*5;
    int b = (int)p[0];
    int x = (int)__fdiv_rn(p[1] - 0.0f,  0.16f);
    int y = (int)__fdiv_rn(p[2] + 39.68f, 0.16f);
    x = min(max(x, 0), NXg-1);
    y = min(max(y, 0), NYg-1);
    atomicAdd(&g_hist[(b*NYg + y)*NXg + x], 1.0f);
}

__global__ void k_blur_x() {
    int i = blockIdx.x*blockDim.x + threadIdx.x;
    if (i >= NB*NYg*NXg) return;
    int x = i % NXg;
    int row = i / NXg;  // b*NYg + y
    float acc = 0.f;
    #pragma unroll
    for (int k = 0; k < KS; k++) {
        int xx = x + k - RAD;
        if (xx >= 0 && xx < NXg)
            acc += g_gauss[k] * g_hist[row*NXg + xx];
    }
    g_tmp[i] = acc;
}

// blur in y + fused per-batch max (NYg*NXg divisible by 256 -> block never straddles batch)
__global__ void k_blur_y() {
    int i = blockIdx.x*blockDim.x + threadIdx.x;
    int x = i % NXg;
    int y = (i / NXg) % NYg;
    int b = i / (NXg*NYg);
    float acc = 0.f;
    #pragma unroll
    for (int k = 0; k < KS; k++) {
        int yy = y + k - RAD;
        if (yy >= 0 && yy < NYg)
            acc += g_gauss[k] * g_tmp[(b*NYg + yy)*NXg + x];
    }
    g_hist[i] = acc;   // blurred result back into g_hist

    __shared__ float sm[256];
    sm[threadIdx.x] = acc; __syncthreads();
    for (int s = 128; s > 0; s >>= 1) {
        if (threadIdx.x < s) sm[threadIdx.x] = fmaxf(sm[threadIdx.x], sm[threadIdx.x+s]);
        __syncthreads();
    }
    if (threadIdx.x == 0) atomicMax(&g_max[b], __float_as_int(sm[0]));
}

// jax.image.resize 'linear' antialias=True, 2x downsample:
// taps at 2i-1..2i+2 with weights [1,3,3,1], edge-clipped + renormalized.
__device__ __forceinline__ void taps4(int i, int n, int* j, float* w) {
    const float base[4] = {1.f, 3.f, 3.f, 1.f};
    float s = 0.f;
    #pragma unroll
    for (int k = 0; k < 4; k++) {
        int jj = 2*i - 1 + k;
        j[k] = jj;
        if (jj >= 0 && jj < n) { w[k] = base[k]; s += base[k]; }
        else w[k] = 0.f;
    }
    #pragma unroll
    for (int k = 0; k < 4; k++) w[k] /= s;
}

__global__ void k_down() {
    int i = blockIdx.x*blockDim.x + threadIdx.x;
    if (i >= NB*HW) return;
    int x = i % Wc;
    int y = (i / Wc) % Hc;
    int b = i / HW;
    int jy[4], jx[4]; float wy[4], wx[4];
    taps4(y, NYg, jy, wy);
    taps4(x, NXg, jx, wx);
    float acc = 0.f;
    #pragma unroll
    for (int a = 0; a < 4; a++) {
        if (wy[a] == 0.f) continue;
        float r = 0.f;
        #pragma unroll
        for (int c = 0; c < 4; c++) {
            if (wx[c] == 0.f) continue;
            r += wx[c] * g_hist[(b*NYg + jy[a])*NXg + jx[c]];
        }
        acc += wy[a] * r;
    }
    float mx = __int_as_float(g_max[b]);
    g_dm[i] = (mx > 0.f) ? acc / mx : acc;
}

__global__ void k_conv1(const float* __restrict__ w1) {
    int bc = blockIdx.y;                 // b*C1 + c
    int b = bc / C1, c = bc % C1;
    int hw = blockIdx.x*blockDim.x + threadIdx.x;
    float v = 0.f;
    if (hw < HW) {
        int x = hw % Wc, y = hw / Wc;
        const float* wp = w1 + c*9;
        const float* in = g_dm + b*HW;
        #pragma unroll
        for (int dy = 0; dy < 3; dy++) {
            int yy = y + dy - 1;
            if (yy < 0 || yy >= Hc) continue;
            #pragma unroll
            for (int dx = 0; dx < 3; dx++) {
                int xx = x + dx - 1;
                if (xx < 0 || xx >= Wc) continue;
                v = fmaf(__ldg(&wp[dy*3+dx]), in[yy*Wc+xx], v);
            }
        }
        g_c1[bc*HW + hw] = v;
    }
    __shared__ float s1[256], s2[256];
    float vv = (hw < HW) ? v : 0.f;
    s1[threadIdx.x] = vv; s2[threadIdx.x] = vv*vv;
    __syncthreads();
    for (int s = 128; s > 0; s >>= 1) {
        if (threadIdx.x < s) { s1[threadIdx.x] += s1[threadIdx.x+s]; s2[threadIdx.x] += s2[threadIdx.x+s]; }
        __syncthreads();
    }
    if (threadIdx.x == 0) {
        atomicAdd(&g_stats1[c], s1[0]);
        atomicAdd(&g_stats1[C1 + c], s2[0]);
    }
}

__global__ void k_bnp1(const float* __restrict__ gamma, const float* __restrict__ beta) {
    int c = threadIdx.x;
    if (c >= C1) return;
    float mean = g_stats1[c] / (float)NBN;
    float var  = g_stats1[C1+c] / (float)NBN - mean*mean;
    float inv  = rsqrtf(var + 1e-3f);
    float sc   = gamma[c] * inv;
    g_bn1[c] = sc;
    g_bn1[C1+c] = beta[c] - mean*sc;
}

__global__ void k_relu1() {
    int i = blockIdx.x*blockDim.x + threadIdx.x;
    if (i >= NB*C1*HW) return;
    int c = (i / HW) % C1;
    g_c1[i] = fmaxf(fmaf(g_c1[i], g_bn1[c], g_bn1[C1+c]), 0.f);
}

__global__ void k_conv2(const float* __restrict__ w2) {
    int bc = blockIdx.y;                 // b*C2 + co
    int b = bc / C2, co = bc % C2;
    __shared__ float ws[C1*9];
    if (threadIdx.x < C1*9) ws[threadIdx.x] = w2[co*C1*9 + threadIdx.x];
    __syncthreads();
    int hw = blockIdx.x*blockDim.x + threadIdx.x;
    float v = 0.f;
    if (hw < HW) {
        int x = hw % Wc, y = hw / Wc;
        #pragma unroll
        for (int ci = 0; ci < C1; ci++) {
            const float* in = g_c1 + (b*C1 + ci)*HW;
            const float* wp = ws + ci*9;
            #pragma unroll
            for (int dy = 0; dy < 3; dy++) {
                int yy = y + dy - 1;
                if (yy < 0 || yy >= Hc) continue;
                #pragma unroll
                for (int dx = 0; dx < 3; dx++) {
                    int xx = x + dx - 1;
                    if (xx < 0 || xx >= Wc) continue;
                    v = fmaf(wp[dy*3+dx], in[yy*Wc+xx], v);
                }
            }
        }
        g_c2[bc*HW + hw] = v;
    }
    __shared__ float s1[256], s2[256];
    float vv = (hw < HW) ? v : 0.f;
    s1[threadIdx.x] = vv; s2[threadIdx.x] = vv*vv;
    __syncthreads();
    for (int s = 128; s > 0; s >>= 1) {
        if (threadIdx.x < s) { s1[threadIdx.x] += s1[threadIdx.x+s]; s2[threadIdx.x] += s2[threadIdx.x+s]; }
        __syncthreads();
    }
    if (threadIdx.x == 0) {
        atomicAdd(&g_stats2[co], s1[0]);
        atomicAdd(&g_stats2[C2 + co], s2[0]);
    }
}

__global__ void k_bnp2(const float* __restrict__ gamma, const float* __restrict__ beta) {
    int c = threadIdx.x;
    if (c >= C2) return;
    float mean = g_stats2[c] / (float)NBN;
    float var  = g_stats2[C2+c] / (float)NBN - mean*mean;
    float inv  = rsqrtf(var + 1e-3f);
    float sc   = gamma[c] * inv;
    g_bn2[c] = sc;
    g_bn2[C2+c] = beta[c] - mean*sc;
}

__global__ void k_out(float* __restrict__ out) {
    int i = blockIdx.x*blockDim.x + threadIdx.x;
    if (i >= NB*C2*HW) return;
    int hw = i % HW;
    int c  = (i / HW) % C2;
    int b  = i / (C2*HW);
    float v = fmaxf(fmaf(g_c2[i], g_bn2[c], g_bn2[C2+c]), 0.f);
    out[((size_t)b*COUT + CSP + c)*HW + hw] = v;
}

extern "C" void kernel_launch(void* const* d_in, const int* in_sizes, int n_in,
                              void* d_out, int out_size) {
    const float* spatial = (const float*)d_in[0];
    const float* points  = (const float*)d_in[1];
    const float* w1      = (const float*)d_in[2];
    const float* gamma1  = (const float*)d_in[3];
    const float* beta1   = (const float*)d_in[4];
    const float* w2      = (const float*)d_in[5];
    const float* gamma2  = (const float*)d_in[6];
    const float* beta2   = (const float*)d_in[7];
    float* out = (float*)d_out;
    int npts = in_sizes[1] / 5;

    // Side stream + events, created once (before first capture), reused every call.
    static cudaStream_t s_copy = [](){ cudaStream_t t; cudaStreamCreate(&t); return t; }();
    static cudaEvent_t ev_fork = [](){ cudaEvent_t e; cudaEventCreateWithFlags(&e, cudaEventDisableTiming); return e; }();
    static cudaEvent_t ev_join = [](){ cudaEvent_t e; cudaEventCreateWithFlags(&e, cudaEventDisableTiming); return e; }();

    // Fork: concat copy of the 384 spatial channels runs concurrently with the chain.
    cudaEventRecord(ev_fork, 0);
    cudaStreamWaitEvent(s_copy, ev_fork, 0);
    k_copy<<<1184, 256, 0, s_copy>>>((const float4*)spatial, (float4*)out);
    cudaEventRecord(ev_join, s_copy);

    int total = NB*NYg*NXg;
    k_init  <<<(total + 255)/256, 256>>>();
    k_hist  <<<(npts + 255)/256, 256>>>(points, npts);
    k_blur_x<<<(total + 255)/256, 256>>>();
    k_blur_y<<<total/256, 256>>>();
    k_down  <<<(NB*HW + 255)/256, 256>>>();
    { dim3 g((HW + 255)/256, NB*C1); k_conv1<<<g, 256>>>(w1); }
    k_bnp1  <<<1, 32>>>(gamma1, beta1);
    k_relu1 <<<(NB*C1*HW + 255)/256, 256>>>();
    { dim3 g((HW + 255)/256, NB*C2); k_conv2<<<g, 256>>>(w2); }
    k_bnp2  <<<1, 32>>>(gamma2, beta2);
    k_out   <<<(NB*C2*HW + 255)/256, 256>>>(out);

    // Join: graph sink depends on both branches.
    cudaStreamWaitEvent(0, ev_join, 0);
}